// round 1
// baseline (speedup 1.0000x reference)
#include <cuda_runtime.h>
#include <cstdint>
#include <math.h>

#define BB 2
#define SS 2048
#define DD 1024
#define HH 16
#define DHD 64
#define MTOT (BB*SS)   // 4096

// ---------------- scratch (device globals; no runtime allocation) ----------
__device__ float g_Q[MTOT * DD];
__device__ float g_K[MTOT * DD];
__device__ float g_V[MTOT * DD];
__device__ float g_A[MTOT * DD];

// ---------------------------------------------------------------------------
// GEMM: C[M,N] = A[M,K] @ W[N,K]^T   (M=4096, N=K=1024 fixed)
// 128x128 block tile, BK=8, 256 threads, 8x8 micro-tile (split 4+4 rows/cols).
// Optional fused RoPE epilogue (for Q and K projections).
// ---------------------------------------------------------------------------
template<bool ROPE>
__global__ __launch_bounds__(256, 2)
void gemm_nt(const float* __restrict__ A, const float* __restrict__ W,
             float* __restrict__ C, const int* __restrict__ pos) {
    __shared__ float As[8][128];
    __shared__ float Bs[8][128];

    const int tid  = threadIdx.x;
    const int brow = blockIdx.x * 128;
    const int bcol = blockIdx.y * 128;

    // global tile load mapping: each thread loads one float4 from A and W
    const int lrow = tid >> 1;          // 0..127
    const int lcol = (tid & 1) * 4;     // 0 or 4
    const float* Ap = A + (size_t)(brow + lrow) * DD + lcol;
    const float* Wp = W + (size_t)(bcol + lrow) * DD + lcol;

    float4 aR = *(const float4*)Ap;
    float4 bR = *(const float4*)Wp;

    // compute mapping: rows rowB..rowB+3 and rowB+64..+67, cols likewise
    const int rowB = (tid >> 4) * 4;    // 0..60
    const int colB = (tid & 15) * 4;    // 0..60

    float acc[8][8];
#pragma unroll
    for (int i = 0; i < 8; ++i)
#pragma unroll
        for (int j = 0; j < 8; ++j) acc[i][j] = 0.0f;

    const int NIT = DD / 8;             // 128 K-iterations
    for (int kt = 0; kt < NIT; ++kt) {
        As[lcol + 0][lrow] = aR.x;
        As[lcol + 1][lrow] = aR.y;
        As[lcol + 2][lrow] = aR.z;
        As[lcol + 3][lrow] = aR.w;
        Bs[lcol + 0][lrow] = bR.x;
        Bs[lcol + 1][lrow] = bR.y;
        Bs[lcol + 2][lrow] = bR.z;
        Bs[lcol + 3][lrow] = bR.w;
        __syncthreads();

        if (kt + 1 < NIT) {             // prefetch next slice into registers
            aR = *(const float4*)(Ap + (size_t)(kt + 1) * 8);
            bR = *(const float4*)(Wp + (size_t)(kt + 1) * 8);
        }

#pragma unroll
        for (int k = 0; k < 8; ++k) {
            float fa[8], fb[8];
            *(float4*)(fa)     = *(const float4*)&As[k][rowB];
            *(float4*)(fa + 4) = *(const float4*)&As[k][rowB + 64];
            *(float4*)(fb)     = *(const float4*)&Bs[k][colB];
            *(float4*)(fb + 4) = *(const float4*)&Bs[k][colB + 64];
#pragma unroll
            for (int i = 0; i < 8; ++i)
#pragma unroll
                for (int j = 0; j < 8; ++j)
                    acc[i][j] = fmaf(fa[i], fb[j], acc[i][j]);
        }
        __syncthreads();
    }

    // ---------------- epilogue (optionally RoPE) ----------------
    float invfA = 0.f, invfB = 0.f;
    if (ROPE) {
        const int d0 = (bcol + colB) & (DHD - 1);   // same for both col groups
        invfA = (float)pow(10000.0, -(double)d0 / (double)DHD);
        invfB = (float)pow(10000.0, -(double)(d0 + 2) / (double)DHD);
    }

#pragma unroll
    for (int ig = 0; ig < 2; ++ig) {
#pragma unroll
        for (int ii = 0; ii < 4; ++ii) {
            const int i   = ig * 4 + ii;
            const int row = brow + rowB + ii + ig * 64;
            float sn0 = 0.f, cs0 = 0.f, sn1 = 0.f, cs1 = 0.f;
            if (ROPE) {
                const float p = (float)pos[row & (SS - 1)];
                sincosf(p * invfA, &sn0, &cs0);
                sincosf(p * invfB, &sn1, &cs1);
            }
#pragma unroll
            for (int jg = 0; jg < 2; ++jg) {
                const int col = bcol + colB + jg * 64;
                const float e0 = acc[i][jg * 4 + 0], o0 = acc[i][jg * 4 + 1];
                const float e1 = acc[i][jg * 4 + 2], o1 = acc[i][jg * 4 + 3];
                float4 r;
                if (ROPE) {
                    r.x = e0 * cs0 - o0 * sn0;
                    r.y = e0 * sn0 + o0 * cs0;
                    r.z = e1 * cs1 - o1 * sn1;
                    r.w = e1 * sn1 + o1 * cs1;
                } else {
                    r.x = e0; r.y = o0; r.z = e1; r.w = o1;
                }
                *(float4*)&C[(size_t)row * DD + col] = r;
            }
        }
    }
}

// ---------------------------------------------------------------------------
// Causal flash attention, fp32. One block = 64 queries of one (b,h).
// K stored transposed in smem so QK^T reads are broadcast x coalesced-float4.
// ---------------------------------------------------------------------------
#define FP 68   // smem pitch (floats): multiple of 4 for float4 alignment

__global__ __launch_bounds__(256, 2)
void flash_attn(const float* __restrict__ Q, const float* __restrict__ K,
                const float* __restrict__ V, float* __restrict__ O) {
    extern __shared__ float sm[];
    float* Qs = sm;                 // [64][FP]  (row-major, pre-scaled)
    float* Kt = Qs + 64 * FP;       // [64][FP]  (d-major: Kt[d][key])
    float* Vs = Kt + 64 * FP;       // [64][FP]  (key-major)
    float* Ps = Vs + 64 * FP;       // [64][FP]

    const int tid = threadIdx.x;
    const int ty = tid >> 4, tx = tid & 15;
    const int r0 = ty * 4, c0 = tx * 4;

    const int bh = blockIdx.y;
    const int b = bh >> 4, h = bh & 15;
    const int q0 = (gridDim.x - 1 - (int)blockIdx.x) * 64;  // heavy blocks first

    const size_t qbase = ((size_t)(b * SS + q0)) * DD + h * DHD;

    // load Q tile, pre-scaled by 1/sqrt(DH)
    for (int f = tid; f < 64 * 16; f += 256) {
        const int row = f >> 4, c4 = (f & 15) << 2;
        float4 v = *(const float4*)(Q + qbase + (size_t)row * DD + c4);
        float* dst = &Qs[row * FP + c4];
        dst[0] = v.x * 0.125f; dst[1] = v.y * 0.125f;
        dst[2] = v.z * 0.125f; dst[3] = v.w * 0.125f;
    }

    float m_run[4], l_run[4], o_acc[4][4];
#pragma unroll
    for (int i = 0; i < 4; ++i) {
        m_run[i] = -1e30f; l_run[i] = 0.f;
#pragma unroll
        for (int j = 0; j < 4; ++j) o_acc[i][j] = 0.f;
    }

    const int ktiles = q0 / 64 + 1;
    for (int kt = 0; kt < ktiles; ++kt) {
        __syncthreads();   // previous PV done; safe to overwrite K/V (and Q visible)
        const size_t kb = ((size_t)(b * SS + kt * 64)) * DD + h * DHD;
        for (int f = tid; f < 64 * 16; f += 256) {
            const int row = f >> 4, c4 = (f & 15) << 2;
            float4 kv = *(const float4*)(K + kb + (size_t)row * DD + c4);
            Kt[(c4 + 0) * FP + row] = kv.x;
            Kt[(c4 + 1) * FP + row] = kv.y;
            Kt[(c4 + 2) * FP + row] = kv.z;
            Kt[(c4 + 3) * FP + row] = kv.w;
            *(float4*)&Vs[row * FP + c4] =
                *(const float4*)(V + kb + (size_t)row * DD + c4);
        }
        __syncthreads();

        // S = Qs @ K^T  (4x4 micro-tile per thread)
        float s[4][4];
#pragma unroll
        for (int i = 0; i < 4; ++i)
#pragma unroll
            for (int j = 0; j < 4; ++j) s[i][j] = 0.f;

#pragma unroll 4
        for (int d = 0; d < 64; ++d) {
            const float4 kv = *(const float4*)&Kt[d * FP + c0];
#pragma unroll
            for (int i = 0; i < 4; ++i) {
                const float q = Qs[(r0 + i) * FP + d];
                s[i][0] = fmaf(q, kv.x, s[i][0]);
                s[i][1] = fmaf(q, kv.y, s[i][1]);
                s[i][2] = fmaf(q, kv.z, s[i][2]);
                s[i][3] = fmaf(q, kv.w, s[i][3]);
            }
        }

        if (kt == ktiles - 1) {          // diagonal tile: causal mask (kt*64 == q0)
#pragma unroll
            for (int i = 0; i < 4; ++i)
#pragma unroll
                for (int j = 0; j < 4; ++j)
                    if (c0 + j > r0 + i) s[i][j] = -1e30f;
        }

        // online softmax update (row group = 16 consecutive lanes)
#pragma unroll
        for (int i = 0; i < 4; ++i) {
            float tm = fmaxf(fmaxf(s[i][0], s[i][1]), fmaxf(s[i][2], s[i][3]));
#pragma unroll
            for (int off = 8; off; off >>= 1)
                tm = fmaxf(tm, __shfl_xor_sync(0xffffffffu, tm, off));
            const float mn    = fmaxf(m_run[i], tm);
            const float alpha = __expf(m_run[i] - mn);
            const float p0 = __expf(s[i][0] - mn);
            const float p1 = __expf(s[i][1] - mn);
            const float p2 = __expf(s[i][2] - mn);
            const float p3 = __expf(s[i][3] - mn);
            float rs = (p0 + p1) + (p2 + p3);
#pragma unroll
            for (int off = 8; off; off >>= 1)
                rs += __shfl_xor_sync(0xffffffffu, rs, off);
            l_run[i] = l_run[i] * alpha + rs;
            m_run[i] = mn;
            o_acc[i][0] *= alpha; o_acc[i][1] *= alpha;
            o_acc[i][2] *= alpha; o_acc[i][3] *= alpha;
            float* pr = &Ps[(r0 + i) * FP + c0];
            pr[0] = p0; pr[1] = p1; pr[2] = p2; pr[3] = p3;
        }
        __syncthreads();

        // O += P @ V
#pragma unroll 4
        for (int k4 = 0; k4 < 64; k4 += 4) {
            float pvf[4][4];
#pragma unroll
            for (int i = 0; i < 4; ++i)
                *(float4*)pvf[i] = *(const float4*)&Ps[(r0 + i) * FP + k4];
#pragma unroll
            for (int t = 0; t < 4; ++t) {
                const float4 vv = *(const float4*)&Vs[(k4 + t) * FP + c0];
#pragma unroll
                for (int i = 0; i < 4; ++i) {
                    o_acc[i][0] = fmaf(pvf[i][t], vv.x, o_acc[i][0]);
                    o_acc[i][1] = fmaf(pvf[i][t], vv.y, o_acc[i][1]);
                    o_acc[i][2] = fmaf(pvf[i][t], vv.z, o_acc[i][2]);
                    o_acc[i][3] = fmaf(pvf[i][t], vv.w, o_acc[i][3]);
                }
            }
        }
    }

    // normalize + write
#pragma unroll
    for (int i = 0; i < 4; ++i) {
        const float inv = 1.0f / l_run[i];
        float4 r;
        r.x = o_acc[i][0] * inv; r.y = o_acc[i][1] * inv;
        r.z = o_acc[i][2] * inv; r.w = o_acc[i][3] * inv;
        *(float4*)&O[((size_t)(b * SS + q0 + r0 + i)) * DD + h * DHD + c0] = r;
    }
}

// ---------------------------------------------------------------------------
extern "C" void kernel_launch(void* const* d_in, const int* in_sizes, int n_in,
                              void* d_out, int out_size) {
    const float* x  = (const float*)d_in[0];
    const float* Wq = (const float*)d_in[1];
    const float* Wk = (const float*)d_in[2];
    const float* Wv = (const float*)d_in[3];
    const float* Wo = (const float*)d_in[4];
    const int*  pos = (const int*)d_in[5];
    float* out = (float*)d_out;

    void *pq, *pk, *pv, *pa;
    cudaGetSymbolAddress(&pq, g_Q);
    cudaGetSymbolAddress(&pk, g_K);
    cudaGetSymbolAddress(&pv, g_V);
    cudaGetSymbolAddress(&pa, g_A);

    const dim3 gg(MTOT / 128, DD / 128);   // 32 x 8

    gemm_nt<true ><<<gg, 256>>>(x, Wq, (float*)pq, pos);
    gemm_nt<true ><<<gg, 256>>>(x, Wk, (float*)pk, pos);
    gemm_nt<false><<<gg, 256>>>(x, Wv, (float*)pv, nullptr);

    const int shm = 4 * 64 * FP * (int)sizeof(float);   // 69632 B
    cudaFuncSetAttribute(flash_attn,
                         cudaFuncAttributeMaxDynamicSharedMemorySize, shm);
    flash_attn<<<dim3(SS / 64, BB * HH), 256, shm>>>(
        (const float*)pq, (const float*)pk, (const float*)pv, (float*)pa);

    gemm_nt<false><<<gg, 256>>>((const float*)pa, Wo, out, nullptr);
}

// round 4
// speedup vs baseline: 1.8918x; 1.8918x over previous
#include <cuda_runtime.h>
#include <cstdint>
#include <math.h>

#define BB 2
#define SS 2048
#define DD 1024
#define HH 16
#define DHD 64
#define MTOT (BB*SS)   // 4096

// ---------------- scratch (device globals; no runtime allocation) ----------
__device__ float g_Q[MTOT * DD];
__device__ float g_K[MTOT * DD];
__device__ float g_V[MTOT * DD];
__device__ float g_A[MTOT * DD];
__device__ float g_X[MTOT * DD];     // tf32-rounded x
__device__ float g_W[4 * DD * DD];   // tf32-rounded Wq,Wk,Wv,Wo

// ---------------------------------------------------------------------------
__device__ __forceinline__ float tf32r(float x) {
    uint32_t y;
    asm("cvt.rna.tf32.f32 %0, %1;" : "=r"(y) : "f"(x));
    return __uint_as_float(y);
}

__device__ __forceinline__ void mma_tf32(float c[4], const uint32_t a[4],
                                         uint32_t b0, uint32_t b1) {
    asm volatile(
        "mma.sync.aligned.m16n8k8.row.col.f32.tf32.tf32.f32 "
        "{%0,%1,%2,%3},{%4,%5,%6,%7},{%8,%9},{%0,%1,%2,%3};"
        : "+f"(c[0]), "+f"(c[1]), "+f"(c[2]), "+f"(c[3])
        : "r"(a[0]), "r"(a[1]), "r"(a[2]), "r"(a[3]), "r"(b0), "r"(b1));
}

// ---------------------------------------------------------------------------
__global__ void round_tf32_kernel(const float* __restrict__ in,
                                  float* __restrict__ out, int n4) {
    int i = blockIdx.x * blockDim.x + threadIdx.x;
    if (i < n4) {
        float4 v = ((const float4*)in)[i];
        v.x = tf32r(v.x); v.y = tf32r(v.y);
        v.z = tf32r(v.z); v.w = tf32r(v.w);
        ((float4*)out)[i] = v;
    }
}

// ---------------------------------------------------------------------------
// GEMM: C[M,N] = A[M,K] @ W[N,K]^T  (M=4096, N=K=1024), tf32 tensor-core MMA.
// MODE: 0 = plain, round output to tf32; 1 = RoPE + round; 2 = plain raw out.
// smem: k-major [32][GP] pitch 136 -> conflict-free fragment loads.
// ---------------------------------------------------------------------------
#define GP 136

template<int MODE>
__global__ __launch_bounds__(256, 2)
void gemm_mma(const float* __restrict__ A, const float* __restrict__ W,
              float* __restrict__ C, const int* __restrict__ pos) {
    __shared__ float As[32 * GP];
    __shared__ float Bs[32 * GP];

    const int tid  = threadIdx.x;
    const int wid  = tid >> 5, lane = tid & 31;
    const int wm   = wid >> 2, wn = wid & 3;      // warp grid 2 x 4
    const int i4   = lane >> 2, j4 = lane & 3;
    const int brow = blockIdx.x * 128;
    const int bcol = blockIdx.y * 128;

    // loader: thread covers row lr, 16 cols at lc
    const int lr = tid >> 1;
    const int lc = (tid & 1) * 16;
    const float* Ap = A + (size_t)(brow + lr) * DD + lc;
    const float* Wp = W + (size_t)(bcol + lr) * DD + lc;

    float4 ra[4], rb[4];
#pragma unroll
    for (int u = 0; u < 4; ++u) {
        ra[u] = *(const float4*)(Ap + u * 4);
        rb[u] = *(const float4*)(Wp + u * 4);
    }

    float acc[16][4];
#pragma unroll
    for (int t = 0; t < 16; ++t)
#pragma unroll
        for (int c = 0; c < 4; ++c) acc[t][c] = 0.f;

    const int NKT = DD / 32;
    for (int kt = 0; kt < NKT; ++kt) {
#pragma unroll
        for (int u = 0; u < 4; ++u) {
            const float* pa = &ra[u].x;
            const float* pb = &rb[u].x;
#pragma unroll
            for (int c = 0; c < 4; ++c) {
                As[(lc + u * 4 + c) * GP + lr] = pa[c];
                Bs[(lc + u * 4 + c) * GP + lr] = pb[c];
            }
        }
        __syncthreads();

        if (kt + 1 < NKT) {
#pragma unroll
            for (int u = 0; u < 4; ++u) {
                ra[u] = *(const float4*)(Ap + (kt + 1) * 32 + u * 4);
                rb[u] = *(const float4*)(Wp + (kt + 1) * 32 + u * 4);
            }
        }

#pragma unroll
        for (int ks = 0; ks < 4; ++ks) {
            uint32_t af[4][4];
#pragma unroll
            for (int mt = 0; mt < 4; ++mt) {
                const int m0 = wm * 64 + mt * 16 + i4;
                const float* p0 = &As[(ks * 8 + j4) * GP + m0];
                const float* p1 = &As[(ks * 8 + 4 + j4) * GP + m0];
                af[mt][0] = __float_as_uint(p0[0]);
                af[mt][1] = __float_as_uint(p0[8]);
                af[mt][2] = __float_as_uint(p1[0]);
                af[mt][3] = __float_as_uint(p1[8]);
            }
#pragma unroll
            for (int nt = 0; nt < 4; ++nt) {
                const int n0 = wn * 32 + nt * 8 + i4;
                uint32_t b0 = __float_as_uint(Bs[(ks * 8 + j4) * GP + n0]);
                uint32_t b1 = __float_as_uint(Bs[(ks * 8 + 4 + j4) * GP + n0]);
#pragma unroll
                for (int mt = 0; mt < 4; ++mt)
                    mma_tf32(acc[mt * 4 + nt], af[mt], b0, b1);
            }
        }
        __syncthreads();
    }

    // ----------------------------- epilogue -----------------------------
    float invf[4];
    if (MODE == 1) {
#pragma unroll
        for (int nt = 0; nt < 4; ++nt) {
            const int col = bcol + wn * 32 + nt * 8 + 2 * j4;
            const int pi  = (col & 63) >> 1;
            invf[nt] = (float)pow(10000.0, -(double)(2 * pi) / 64.0);
        }
    }

#pragma unroll
    for (int mt = 0; mt < 4; ++mt) {
        const int row0 = brow + wm * 64 + mt * 16 + i4;
#pragma unroll
        for (int half = 0; half < 2; ++half) {
            const int row = row0 + half * 8;
            float p = 0.f;
            if (MODE == 1) p = (float)pos[row & (SS - 1)];
#pragma unroll
            for (int nt = 0; nt < 4; ++nt) {
                const int col = bcol + wn * 32 + nt * 8 + 2 * j4;
                const float e = acc[mt * 4 + nt][half * 2 + 0];
                const float o = acc[mt * 4 + nt][half * 2 + 1];
                float2 r;
                if (MODE == 1) {
                    float sn, cs;
                    sincosf(p * invf[nt], &sn, &cs);
                    r.x = e * cs - o * sn;
                    r.y = e * sn + o * cs;
                } else {
                    r.x = e; r.y = o;
                }
                if (MODE != 2) { r.x = tf32r(r.x); r.y = tf32r(r.y); }
                *(float2*)&C[(size_t)row * DD + col] = r;
            }
        }
    }
}

// ---------------------------------------------------------------------------
// Causal flash attention with tf32 MMA. BQ=128, BK=64, 8 warps (m16 each).
// Ps aliases Kt (same 34.8KB); Q stays in smem; 88KB smem -> 2 blocks/SM.
// ---------------------------------------------------------------------------
#define QP 68
#define KTP 136
#define VP 72
#define SMF ((128 * QP + 64 * KTP + 64 * VP) * 4)   // 88064 B

__global__ __launch_bounds__(256, 2)
void flash_mma(const float* __restrict__ Q, const float* __restrict__ K,
               const float* __restrict__ V, float* __restrict__ O) {
    extern __shared__ float sm[];
    float* Qs = sm;                    // [128][QP]
    float* Kt = sm + 128 * QP;         // [64][KTP]  (d-major)
    float* Ps = Kt;                    // [128][QP]  alias (same size)
    float* Vs = Kt + 64 * KTP;         // [64][VP]   (key-major)

    const int tid = threadIdx.x, wid = tid >> 5, lane = tid & 31;
    const int i4 = lane >> 2, j4 = lane & 3;
    const int wrow = wid * 16;

    const int bh = blockIdx.y, b = bh >> 4, h = bh & 15;
    const int q0 = ((int)gridDim.x - 1 - (int)blockIdx.x) * 128;
    const size_t qbase = ((size_t)(b * SS + q0)) * DD + h * DHD;

    // stage Q (pre-scaled by 1/sqrt(DH); scale is power of 2 -> stays tf32)
    for (int f = tid; f < 128 * 16; f += 256) {
        const int r = f >> 4, c4 = (f & 15) << 2;
        float4 v = *(const float4*)(Q + qbase + (size_t)r * DD + c4);
        float* d = &Qs[r * QP + c4];
        d[0] = v.x * 0.125f; d[1] = v.y * 0.125f;
        d[2] = v.z * 0.125f; d[3] = v.w * 0.125f;
    }

    float o[8][4];
#pragma unroll
    for (int nt = 0; nt < 8; ++nt)
#pragma unroll
        for (int c = 0; c < 4; ++c) o[nt][c] = 0.f;
    float m0 = -1e30f, m1 = -1e30f, l0 = 0.f, l1 = 0.f;

    const int nk = q0 / 64 + 2;
    for (int kt = 0; kt < nk; ++kt) {
        __syncthreads();   // prev PV done (Ps aliases Kt), Vs free, Q staged
        const size_t kb = ((size_t)(b * SS + kt * 64)) * DD + h * DHD;
        for (int f = tid; f < 64 * 16; f += 256) {
            const int r = f >> 4, c4 = (f & 15) << 2;
            float4 kv = *(const float4*)(K + kb + (size_t)r * DD + c4);
            Kt[(c4 + 0) * KTP + r] = kv.x;
            Kt[(c4 + 1) * KTP + r] = kv.y;
            Kt[(c4 + 2) * KTP + r] = kv.z;
            Kt[(c4 + 3) * KTP + r] = kv.w;
            *(float4*)&Vs[r * VP + c4] =
                *(const float4*)(V + kb + (size_t)r * DD + c4);
        }
        __syncthreads();

        // ---- S = Q @ K^T (warp: m16 x n64, k64) ----
        float s[8][4];
#pragma unroll
        for (int nt = 0; nt < 8; ++nt)
#pragma unroll
            for (int c = 0; c < 4; ++c) s[nt][c] = 0.f;

#pragma unroll
        for (int ks = 0; ks < 8; ++ks) {
            uint32_t a[4];
            a[0] = __float_as_uint(Qs[(wrow + i4)     * QP + ks * 8 + j4]);
            a[1] = __float_as_uint(Qs[(wrow + i4 + 8) * QP + ks * 8 + j4]);
            a[2] = __float_as_uint(Qs[(wrow + i4)     * QP + ks * 8 + j4 + 4]);
            a[3] = __float_as_uint(Qs[(wrow + i4 + 8) * QP + ks * 8 + j4 + 4]);
#pragma unroll
            for (int nt = 0; nt < 8; ++nt) {
                uint32_t b0 = __float_as_uint(Kt[(ks * 8 + j4)     * KTP + nt * 8 + i4]);
                uint32_t b1 = __float_as_uint(Kt[(ks * 8 + 4 + j4) * KTP + nt * 8 + i4]);
                mma_tf32(s[nt], a, b0, b1);
            }
        }

        // ---- causal mask on last two tiles ----
        if (kt >= nk - 2) {
            const int kbase = kt * 64;
            const int rlo = q0 + wrow + i4, rhi = rlo + 8;
#pragma unroll
            for (int nt = 0; nt < 8; ++nt) {
                const int c0 = kbase + nt * 8 + 2 * j4;
                if (c0     > rlo) s[nt][0] = -1e30f;
                if (c0 + 1 > rlo) s[nt][1] = -1e30f;
                if (c0     > rhi) s[nt][2] = -1e30f;
                if (c0 + 1 > rhi) s[nt][3] = -1e30f;
            }
        }

        // ---- online softmax (rows i4 and i4+8; quad = lanes sharing row) ----
        float mx0 = -1e30f, mx1 = -1e30f;
#pragma unroll
        for (int nt = 0; nt < 8; ++nt) {
            mx0 = fmaxf(mx0, fmaxf(s[nt][0], s[nt][1]));
            mx1 = fmaxf(mx1, fmaxf(s[nt][2], s[nt][3]));
        }
#pragma unroll
        for (int off = 1; off <= 2; off <<= 1) {
            mx0 = fmaxf(mx0, __shfl_xor_sync(0xffffffffu, mx0, off));
            mx1 = fmaxf(mx1, __shfl_xor_sync(0xffffffffu, mx1, off));
        }
        const float mn0 = fmaxf(m0, mx0), mn1 = fmaxf(m1, mx1);
        const float al0 = __expf(m0 - mn0), al1 = __expf(m1 - mn1);
        float s0 = 0.f, s1 = 0.f;
#pragma unroll
        for (int nt = 0; nt < 8; ++nt) {
            s[nt][0] = __expf(s[nt][0] - mn0);
            s[nt][1] = __expf(s[nt][1] - mn0);
            s[nt][2] = __expf(s[nt][2] - mn1);
            s[nt][3] = __expf(s[nt][3] - mn1);
            s0 += s[nt][0] + s[nt][1];
            s1 += s[nt][2] + s[nt][3];
        }
#pragma unroll
        for (int off = 1; off <= 2; off <<= 1) {
            s0 += __shfl_xor_sync(0xffffffffu, s0, off);
            s1 += __shfl_xor_sync(0xffffffffu, s1, off);
        }
        l0 = l0 * al0 + s0;  m0 = mn0;
        l1 = l1 * al1 + s1;  m1 = mn1;
#pragma unroll
        for (int nt = 0; nt < 8; ++nt) {
            o[nt][0] *= al0; o[nt][1] *= al0;
            o[nt][2] *= al1; o[nt][3] *= al1;
        }

        __syncthreads();   // all warps done reading Kt before Ps overwrites it

        // ---- stage P (tf32) into per-warp rows of Ps ----
#pragma unroll
        for (int nt = 0; nt < 8; ++nt) {
            float2 lo; lo.x = tf32r(s[nt][0]); lo.y = tf32r(s[nt][1]);
            float2 hi; hi.x = tf32r(s[nt][2]); hi.y = tf32r(s[nt][3]);
            *(float2*)&Ps[(wrow + i4)     * QP + nt * 8 + 2 * j4] = lo;
            *(float2*)&Ps[(wrow + i4 + 8) * QP + nt * 8 + 2 * j4] = hi;
        }
        __syncwarp();      // warp reads only its own P rows

        // ---- O += P @ V (warp: m16 x n64, k64 keys) ----
#pragma unroll
        for (int ks = 0; ks < 8; ++ks) {
            uint32_t a[4];
            a[0] = __float_as_uint(Ps[(wrow + i4)     * QP + ks * 8 + j4]);
            a[1] = __float_as_uint(Ps[(wrow + i4 + 8) * QP + ks * 8 + j4]);
            a[2] = __float_as_uint(Ps[(wrow + i4)     * QP + ks * 8 + j4 + 4]);
            a[3] = __float_as_uint(Ps[(wrow + i4 + 8) * QP + ks * 8 + j4 + 4]);
#pragma unroll
            for (int nt = 0; nt < 8; ++nt) {
                uint32_t b0 = __float_as_uint(Vs[(ks * 8 + j4)     * VP + nt * 8 + i4]);
                uint32_t b1 = __float_as_uint(Vs[(ks * 8 + 4 + j4) * VP + nt * 8 + i4]);
                mma_tf32(o[nt], a, b0, b1);
            }
        }
    }

    // ---- normalize, round to tf32 (feeds final GEMM), write ----
    const float inv0 = 1.0f / l0, inv1 = 1.0f / l1;
    const size_t ob = ((size_t)(b * SS + q0 + wrow)) * DD + h * DHD;
#pragma unroll
    for (int nt = 0; nt < 8; ++nt) {
        float2 lo, hi;
        lo.x = tf32r(o[nt][0] * inv0); lo.y = tf32r(o[nt][1] * inv0);
        hi.x = tf32r(o[nt][2] * inv1); hi.y = tf32r(o[nt][3] * inv1);
        *(float2*)&O[ob + (size_t)i4       * DD + nt * 8 + 2 * j4] = lo;
        *(float2*)&O[ob + (size_t)(i4 + 8) * DD + nt * 8 + 2 * j4] = hi;
    }
}

// ---------------------------------------------------------------------------
extern "C" void kernel_launch(void* const* d_in, const int* in_sizes, int n_in,
                              void* d_out, int out_size) {
    const float* x  = (const float*)d_in[0];
    const float* Wq = (const float*)d_in[1];
    const float* Wk = (const float*)d_in[2];
    const float* Wv = (const float*)d_in[3];
    const float* Wo = (const float*)d_in[4];
    const int*  pos = (const int*)d_in[5];
    float* out = (float*)d_out;

    void *pq, *pk, *pv, *pa, *px, *pw;
    cudaGetSymbolAddress(&pq, g_Q);
    cudaGetSymbolAddress(&pk, g_K);
    cudaGetSymbolAddress(&pv, g_V);
    cudaGetSymbolAddress(&pa, g_A);
    cudaGetSymbolAddress(&px, g_X);
    cudaGetSymbolAddress(&pw, g_W);

    float* fX = (float*)px;
    float* fW = (float*)pw;

    // pre-round inputs to tf32 (RNA) so MMA's truncating read is exact
    {
        const int n4x = MTOT * DD / 4, n4w = DD * DD / 4;
        round_tf32_kernel<<<(n4x + 255) / 256, 256>>>(x, fX, n4x);
        round_tf32_kernel<<<(n4w + 255) / 256, 256>>>(Wq, fW + 0 * DD * DD, n4w);
        round_tf32_kernel<<<(n4w + 255) / 256, 256>>>(Wk, fW + 1 * DD * DD, n4w);
        round_tf32_kernel<<<(n4w + 255) / 256, 256>>>(Wv, fW + 2 * DD * DD, n4w);
        round_tf32_kernel<<<(n4w + 255) / 256, 256>>>(Wo, fW + 3 * DD * DD, n4w);
    }

    const dim3 gg(MTOT / 128, DD / 128);   // 32 x 8

    gemm_mma<1><<<gg, 256>>>(fX, fW + 0 * DD * DD, (float*)pq, pos);
    gemm_mma<1><<<gg, 256>>>(fX, fW + 1 * DD * DD, (float*)pk, pos);
    gemm_mma<0><<<gg, 256>>>(fX, fW + 2 * DD * DD, (float*)pv, nullptr);

    cudaFuncSetAttribute(flash_mma,
                         cudaFuncAttributeMaxDynamicSharedMemorySize, SMF);
    flash_mma<<<dim3(SS / 128, BB * HH), 256, SMF>>>(
        (const float*)pq, (const float*)pk, (const float*)pv, (float*)pa);

    gemm_mma<2><<<gg, 256>>>((const float*)pa, fW + 3 * DD * DD, out, nullptr);
}

// round 5
// speedup vs baseline: 2.9936x; 1.5824x over previous
#include <cuda_runtime.h>
#include <cstdint>
#include <math.h>

#define BB 2
#define SS 2048
#define DD 1024
#define HH 16
#define DHD 64
#define MTOT (BB*SS)   // 4096

// ---------------- scratch (device globals; no runtime allocation) ----------
__device__ float g_QKV[3 * MTOT * DD];
__device__ float g_A[MTOT * DD];
__device__ float g_X[MTOT * DD];     // tf32-rounded x
__device__ float g_W[4 * DD * DD];   // tf32-rounded Wq,Wk,Wv,Wo

// ---------------------------------------------------------------------------
__device__ __forceinline__ float tf32r(float x) {
    uint32_t y;
    asm("cvt.rna.tf32.f32 %0, %1;" : "=r"(y) : "f"(x));
    return __uint_as_float(y);
}

__device__ __forceinline__ void mma_tf32(float c[4], const uint32_t a[4],
                                         uint32_t b0, uint32_t b1) {
    asm volatile(
        "mma.sync.aligned.m16n8k8.row.col.f32.tf32.tf32.f32 "
        "{%0,%1,%2,%3},{%4,%5,%6,%7},{%8,%9},{%0,%1,%2,%3};"
        : "+f"(c[0]), "+f"(c[1]), "+f"(c[2]), "+f"(c[3])
        : "r"(a[0]), "r"(a[1]), "r"(a[2]), "r"(a[3]), "r"(b0), "r"(b1));
}

__device__ __forceinline__ void cpa16(uint32_t dst, const void* src) {
    asm volatile("cp.async.cg.shared.global [%0], [%1], 16;"
                 :: "r"(dst), "l"(src));
}
#define CP_COMMIT() asm volatile("cp.async.commit_group;")
#define CP_WAIT1()  asm volatile("cp.async.wait_group 1;")

// ---------------------------------------------------------------------------
__global__ void round_x_kernel(const float* __restrict__ in,
                               float* __restrict__ out, int n4) {
    int i = blockIdx.x * blockDim.x + threadIdx.x;
    if (i < n4) {
        float4 v = ((const float4*)in)[i];
        v.x = tf32r(v.x); v.y = tf32r(v.y);
        v.z = tf32r(v.z); v.w = tf32r(v.w);
        ((float4*)out)[i] = v;
    }
}

__global__ void round_w_kernel(const float* __restrict__ w0,
                               const float* __restrict__ w1,
                               const float* __restrict__ w2,
                               const float* __restrict__ w3,
                               float* __restrict__ out) {
    const int i = blockIdx.x * blockDim.x + threadIdx.x;   // < DD*DD/4
    const int z = blockIdx.y;
    const float* src = (z == 0) ? w0 : (z == 1) ? w1 : (z == 2) ? w2 : w3;
    float4 v = ((const float4*)src)[i];
    v.x = tf32r(v.x); v.y = tf32r(v.y);
    v.z = tf32r(v.z); v.w = tf32r(v.w);
    ((float4*)(out + (size_t)z * DD * DD))[i] = v;
}

// ---------------------------------------------------------------------------
// GEMM: C[M,N] = A[M,K] @ W[N,K]^T, tf32 MMA, cp.async 2-stage double buffer.
// gridDim.z selects weight/output slice (fused QKV). Row-major smem, pitch 36.
// mode: 1 = RoPE + tf32 round, 0 = round only, 2 = raw fp32 out.
// ---------------------------------------------------------------------------
#define AP 36
#define GSM (2 * 2 * 128 * AP * 4)   // 73728 B

__global__ __launch_bounds__(256, 2)
void gemm_mma(const float* __restrict__ A, const float* __restrict__ Wbase,
              float* __restrict__ Cbase, const int* __restrict__ pos,
              int modesel) {
    extern __shared__ float sm[];
    float* As = sm;                    // [2][128][AP]
    float* Bs = sm + 2 * 128 * AP;     // [2][128][AP]
    const uint32_t sb = (uint32_t)__cvta_generic_to_shared(sm);
    const uint32_t bs_b = sb + 2 * 128 * AP * 4;

    const int z = blockIdx.z;
    const float* W = Wbase + (size_t)z * DD * DD;
    float* C = Cbase + (size_t)z * MTOT * DD;
    const int mode = (modesel >= 0) ? modesel : ((z == 2) ? 0 : 1);

    const int tid  = threadIdx.x;
    const int wid  = tid >> 5, lane = tid & 31;
    const int wm   = wid >> 2, wn = wid & 3;
    const int i4   = lane >> 2, j4 = lane & 3;
    const int brow = blockIdx.x * 128;
    const int bcol = blockIdx.y * 128;

    const int lr0 = tid >> 3;          // 0..31
    const int lcc = (tid & 7) * 4;     // 0..28

    float acc[16][4];
#pragma unroll
    for (int t = 0; t < 16; ++t)
#pragma unroll
        for (int c = 0; c < 4; ++c) acc[t][c] = 0.f;

    auto issueAB = [&](int st, int kt) {
#pragma unroll
        for (int u = 0; u < 4; ++u) {
            const int r = lr0 + u * 32;
            cpa16(sb   + (uint32_t)((st * 128 + r) * AP + lcc) * 4,
                  A + (size_t)(brow + r) * DD + kt * 32 + lcc);
            cpa16(bs_b + (uint32_t)((st * 128 + r) * AP + lcc) * 4,
                  W + (size_t)(bcol + r) * DD + kt * 32 + lcc);
        }
    };

    issueAB(0, 0);
    CP_COMMIT();

    const int NKT = DD / 32;
    for (int kt = 0; kt < NKT; ++kt) {
        __syncthreads();                       // prev compute done everywhere
        if (kt + 1 < NKT) issueAB((kt + 1) & 1, kt + 1);
        CP_COMMIT();
        CP_WAIT1();
        __syncthreads();                       // current stage visible to all

        const float* Ast = As + (kt & 1) * 128 * AP;
        const float* Bst = Bs + (kt & 1) * 128 * AP;

#pragma unroll
        for (int ks = 0; ks < 4; ++ks) {
            uint32_t af[4][4];
#pragma unroll
            for (int mt = 0; mt < 4; ++mt) {
                const float* p = Ast + (wm * 64 + mt * 16 + i4) * AP + ks * 8 + j4;
                af[mt][0] = __float_as_uint(p[0]);
                af[mt][1] = __float_as_uint(p[8 * AP]);
                af[mt][2] = __float_as_uint(p[4]);
                af[mt][3] = __float_as_uint(p[8 * AP + 4]);
            }
#pragma unroll
            for (int nt = 0; nt < 4; ++nt) {
                const float* q = Bst + (wn * 32 + nt * 8 + i4) * AP + ks * 8 + j4;
                const uint32_t b0 = __float_as_uint(q[0]);
                const uint32_t b1 = __float_as_uint(q[4]);
#pragma unroll
                for (int mt = 0; mt < 4; ++mt)
                    mma_tf32(acc[mt * 4 + nt], af[mt], b0, b1);
            }
        }
    }

    // ----------------------------- epilogue -----------------------------
    float invf[4];
    if (mode == 1) {
#pragma unroll
        for (int nt = 0; nt < 4; ++nt) {
            const int col = bcol + wn * 32 + nt * 8 + 2 * j4;
            const int pi  = (col & 63) >> 1;
            invf[nt] = (float)pow(10000.0, -(double)(2 * pi) / 64.0);
        }
    }

#pragma unroll
    for (int mt = 0; mt < 4; ++mt) {
        const int row0 = brow + wm * 64 + mt * 16 + i4;
#pragma unroll
        for (int half = 0; half < 2; ++half) {
            const int row = row0 + half * 8;
            float p = 0.f;
            if (mode == 1) p = (float)pos[row & (SS - 1)];
#pragma unroll
            for (int nt = 0; nt < 4; ++nt) {
                const int col = bcol + wn * 32 + nt * 8 + 2 * j4;
                const float e = acc[mt * 4 + nt][half * 2 + 0];
                const float o = acc[mt * 4 + nt][half * 2 + 1];
                float2 r;
                if (mode == 1) {
                    float sn, cs;
                    sincosf(p * invf[nt], &sn, &cs);
                    r.x = e * cs - o * sn;
                    r.y = e * sn + o * cs;
                } else {
                    r.x = e; r.y = o;
                }
                if (mode != 2) { r.x = tf32r(r.x); r.y = tf32r(r.y); }
                *(float2*)&C[(size_t)row * DD + col] = r;
            }
        }
    }
}

// ---------------------------------------------------------------------------
// Causal flash attention, tf32 MMA. BQ=128, BK=64, 8 warps (m16 x n64 each).
// Q fragments hoisted to registers; K/V row-major smem, cp.async 2-stage.
// Ps aliases Qs. smem 106496 B -> 2 blocks/SM.
// ---------------------------------------------------------------------------
#define QFP 68
#define KP  68
#define VP2 72
#define SMF ((128 * QFP + 2 * 64 * KP + 2 * 64 * VP2) * 4)   // 106496

__global__ __launch_bounds__(256, 2)
void flash_mma(const float* __restrict__ Q, const float* __restrict__ K,
               const float* __restrict__ V, float* __restrict__ O) {
    extern __shared__ float sm[];
    float* Qs = sm;                       // [128][QFP]
    float* Ps = sm;                       // alias
    float* Ks = sm + 128 * QFP;           // [2][64][KP]
    float* Vs = Ks + 2 * 64 * KP;         // [2][64][VP2]
    const uint32_t sb   = (uint32_t)__cvta_generic_to_shared(sm);
    const uint32_t ks_b = sb + 128 * QFP * 4;
    const uint32_t vs_b = ks_b + 2 * 64 * KP * 4;

    const int tid = threadIdx.x, wid = tid >> 5, lane = tid & 31;
    const int i4 = lane >> 2, j4 = lane & 3;
    const int wrow = wid * 16;

    const int bh = blockIdx.y, b = bh >> 4, h = bh & 15;
    const int q0 = ((int)gridDim.x - 1 - (int)blockIdx.x) * 128;
    const size_t qbase = ((size_t)(b * SS + q0)) * DD + h * DHD;

    // stage Q (pre-scaled by 1/sqrt(DH))
    for (int f = tid; f < 128 * 16; f += 256) {
        const int r = f >> 4, c4 = (f & 15) << 2;
        float4 v = *(const float4*)(Q + qbase + (size_t)r * DD + c4);
        float* d = &Qs[r * QFP + c4];
        d[0] = v.x * 0.125f; d[1] = v.y * 0.125f;
        d[2] = v.z * 0.125f; d[3] = v.w * 0.125f;
    }
    __syncthreads();

    // hoist Q fragments (loop-invariant)
    uint32_t qf[8][4];
#pragma unroll
    for (int ks = 0; ks < 8; ++ks) {
        const float* p = Qs + (wrow + i4) * QFP + ks * 8 + j4;
        qf[ks][0] = __float_as_uint(p[0]);
        qf[ks][1] = __float_as_uint(p[8 * QFP]);
        qf[ks][2] = __float_as_uint(p[4]);
        qf[ks][3] = __float_as_uint(p[8 * QFP + 4]);
    }

    float o[8][4];
#pragma unroll
    for (int nt = 0; nt < 8; ++nt)
#pragma unroll
        for (int c = 0; c < 4; ++c) o[nt][c] = 0.f;
    float m0 = -1e30f, m1 = -1e30f, l0 = 0.f, l1 = 0.f;

    const int r16 = tid >> 4;          // 0..15
    const int c16 = (tid & 15) * 4;    // 0..60

    auto issueKV = [&](int st, int kt) {
        const float* kb = K + ((size_t)(b * SS + kt * 64)) * DD + h * DHD;
        const float* vb = V + ((size_t)(b * SS + kt * 64)) * DD + h * DHD;
#pragma unroll
        for (int u = 0; u < 4; ++u) {
            const int r = r16 + u * 16;
            cpa16(ks_b + (uint32_t)((st * 64 + r) * KP + c16) * 4,
                  kb + (size_t)r * DD + c16);
            cpa16(vs_b + (uint32_t)((st * 64 + r) * VP2 + c16) * 4,
                  vb + (size_t)r * DD + c16);
        }
    };

    const int nk = q0 / 64 + 2;
    issueKV(0, 0);
    CP_COMMIT();

    for (int kt = 0; kt < nk; ++kt) {
        __syncthreads();                   // all warps done with prev stage
        if (kt + 1 < nk) issueKV((kt + 1) & 1, kt + 1);
        CP_COMMIT();
        CP_WAIT1();
        __syncthreads();                   // stage kt visible to all

        const float* Kst = Ks + (kt & 1) * 64 * KP;
        const float* Vst = Vs + (kt & 1) * 64 * VP2;

        // ---- S = Q @ K^T (warp: m16 x n64, k64) ----
        float s[8][4];
#pragma unroll
        for (int nt = 0; nt < 8; ++nt)
#pragma unroll
            for (int c = 0; c < 4; ++c) s[nt][c] = 0.f;

#pragma unroll
        for (int ks = 0; ks < 8; ++ks) {
#pragma unroll
            for (int nt = 0; nt < 8; ++nt) {
                const float* p = Kst + (nt * 8 + i4) * KP + ks * 8 + j4;
                const uint32_t b0 = __float_as_uint(p[0]);
                const uint32_t b1 = __float_as_uint(p[4]);
                mma_tf32(s[nt], qf[ks], b0, b1);
            }
        }

        // ---- causal mask on last two tiles ----
        if (kt >= nk - 2) {
            const int kbase = kt * 64;
            const int rlo = q0 + wrow + i4, rhi = rlo + 8;
#pragma unroll
            for (int nt = 0; nt < 8; ++nt) {
                const int c0 = kbase + nt * 8 + 2 * j4;
                if (c0     > rlo) s[nt][0] = -1e30f;
                if (c0 + 1 > rlo) s[nt][1] = -1e30f;
                if (c0     > rhi) s[nt][2] = -1e30f;
                if (c0 + 1 > rhi) s[nt][3] = -1e30f;
            }
        }

        // ---- online softmax ----
        float mx0 = -1e30f, mx1 = -1e30f;
#pragma unroll
        for (int nt = 0; nt < 8; ++nt) {
            mx0 = fmaxf(mx0, fmaxf(s[nt][0], s[nt][1]));
            mx1 = fmaxf(mx1, fmaxf(s[nt][2], s[nt][3]));
        }
#pragma unroll
        for (int off = 1; off <= 2; off <<= 1) {
            mx0 = fmaxf(mx0, __shfl_xor_sync(0xffffffffu, mx0, off));
            mx1 = fmaxf(mx1, __shfl_xor_sync(0xffffffffu, mx1, off));
        }
        const float mn0 = fmaxf(m0, mx0), mn1 = fmaxf(m1, mx1);
        const float al0 = __expf(m0 - mn0), al1 = __expf(m1 - mn1);
        float s0 = 0.f, s1 = 0.f;
#pragma unroll
        for (int nt = 0; nt < 8; ++nt) {
            s[nt][0] = __expf(s[nt][0] - mn0);
            s[nt][1] = __expf(s[nt][1] - mn0);
            s[nt][2] = __expf(s[nt][2] - mn1);
            s[nt][3] = __expf(s[nt][3] - mn1);
            s0 += s[nt][0] + s[nt][1];
            s1 += s[nt][2] + s[nt][3];
        }
#pragma unroll
        for (int off = 1; off <= 2; off <<= 1) {
            s0 += __shfl_xor_sync(0xffffffffu, s0, off);
            s1 += __shfl_xor_sync(0xffffffffu, s1, off);
        }
        l0 = l0 * al0 + s0;  m0 = mn0;
        l1 = l1 * al1 + s1;  m1 = mn1;
#pragma unroll
        for (int nt = 0; nt < 8; ++nt) {
            o[nt][0] *= al0; o[nt][1] *= al0;
            o[nt][2] *= al1; o[nt][3] *= al1;
        }

        // ---- stage P (tf32) into warp-private rows of Ps ----
#pragma unroll
        for (int nt = 0; nt < 8; ++nt) {
            float2 lo; lo.x = tf32r(s[nt][0]); lo.y = tf32r(s[nt][1]);
            float2 hi; hi.x = tf32r(s[nt][2]); hi.y = tf32r(s[nt][3]);
            *(float2*)&Ps[(wrow + i4)     * QFP + nt * 8 + 2 * j4] = lo;
            *(float2*)&Ps[(wrow + i4 + 8) * QFP + nt * 8 + 2 * j4] = hi;
        }
        __syncwarp();

        // ---- O += P @ V ----
#pragma unroll
        for (int ks = 0; ks < 8; ++ks) {
            uint32_t a[4];
            const float* p = Ps + (wrow + i4) * QFP + ks * 8 + j4;
            a[0] = __float_as_uint(p[0]);
            a[1] = __float_as_uint(p[8 * QFP]);
            a[2] = __float_as_uint(p[4]);
            a[3] = __float_as_uint(p[8 * QFP + 4]);
#pragma unroll
            for (int nt = 0; nt < 8; ++nt) {
                const float* q = Vst + (ks * 8 + j4) * VP2 + nt * 8 + i4;
                const uint32_t b0 = __float_as_uint(q[0]);
                const uint32_t b1 = __float_as_uint(q[4 * VP2]);
                mma_tf32(o[nt], a, b0, b1);
            }
        }
    }

    // ---- normalize, round to tf32, write ----
    const float inv0 = 1.0f / l0, inv1 = 1.0f / l1;
    const size_t ob = ((size_t)(b * SS + q0 + wrow)) * DD + h * DHD;
#pragma unroll
    for (int nt = 0; nt < 8; ++nt) {
        float2 lo, hi;
        lo.x = tf32r(o[nt][0] * inv0); lo.y = tf32r(o[nt][1] * inv0);
        hi.x = tf32r(o[nt][2] * inv1); hi.y = tf32r(o[nt][3] * inv1);
        *(float2*)&O[ob + (size_t)i4       * DD + nt * 8 + 2 * j4] = lo;
        *(float2*)&O[ob + (size_t)(i4 + 8) * DD + nt * 8 + 2 * j4] = hi;
    }
}

// ---------------------------------------------------------------------------
extern "C" void kernel_launch(void* const* d_in, const int* in_sizes, int n_in,
                              void* d_out, int out_size) {
    const float* x  = (const float*)d_in[0];
    const float* Wq = (const float*)d_in[1];
    const float* Wk = (const float*)d_in[2];
    const float* Wv = (const float*)d_in[3];
    const float* Wo = (const float*)d_in[4];
    const int*  pos = (const int*)d_in[5];
    float* out = (float*)d_out;

    void *pqkv, *pa, *px, *pw;
    cudaGetSymbolAddress(&pqkv, g_QKV);
    cudaGetSymbolAddress(&pa, g_A);
    cudaGetSymbolAddress(&px, g_X);
    cudaGetSymbolAddress(&pw, g_W);

    float* fQKV = (float*)pqkv;
    float* fA   = (float*)pa;
    float* fX   = (float*)px;
    float* fW   = (float*)pw;

    // pre-round inputs to tf32 (RNA)
    {
        const int n4x = MTOT * DD / 4;
        round_x_kernel<<<(n4x + 255) / 256, 256>>>(x, fX, n4x);
        round_w_kernel<<<dim3(DD * DD / 4 / 256, 4), 256>>>(Wq, Wk, Wv, Wo, fW);
    }

    cudaFuncSetAttribute(gemm_mma,
                         cudaFuncAttributeMaxDynamicSharedMemorySize, GSM);
    cudaFuncSetAttribute(flash_mma,
                         cudaFuncAttributeMaxDynamicSharedMemorySize, SMF);

    // fused QKV projection (+RoPE on Q,K)
    gemm_mma<<<dim3(MTOT / 128, DD / 128, 3), 256, GSM>>>(
        fX, fW, fQKV, pos, -1);

    flash_mma<<<dim3(SS / 128, BB * HH), 256, SMF>>>(
        fQKV, fQKV + (size_t)MTOT * DD, fQKV + 2 * (size_t)MTOT * DD, fA);

    // output projection
    gemm_mma<<<dim3(MTOT / 128, DD / 128, 1), 256, GSM>>>(
        fA, fW + 3 * (size_t)DD * DD, out, pos, 2);
}